// round 16
// baseline (speedup 1.0000x reference)
#include <cuda_runtime.h>
#include <cuda_bf16.h>
#include <cuda_fp16.h>
#include <math.h>
#include <stdint.h>
#include <string.h>

#define BATCH 4
#define CIN   256
#define HW    4096
#define DIM   64
#define LOG2E 1.4426950408889634f

typedef unsigned int u32;
typedef unsigned long long u64;

// ---------------------------------------------------------------------------
// Device scratch
// ---------------------------------------------------------------------------
__device__ __half g_w[3 * DIM * CIN];              // wq|wk|wv stacked [192][256]
__device__ __half g_wsa[CIN * DIM];
__device__ __half g_q[BATCH * HW * DIM];           // pre-scaled by log2(e)
__device__ __half g_k[BATCH * HW * DIM];
__device__ __nv_bfloat16 g_vth[BATCH * DIM * HW];  // [b][d][j] bf16
__device__ __half g_sa[BATCH * HW * DIM];          // attention out [b][n][d]

// ---------------------------------------------------------------------------
// Helpers
// ---------------------------------------------------------------------------
__device__ __forceinline__ uint32_t smem_u32(const void* p) {
    uint32_t a;
    asm("{ .reg .u64 t; cvta.to.shared.u64 t, %1; cvt.u32.u64 %0, t; }" : "=r"(a) : "l"(p));
    return a;
}
__device__ __forceinline__ u32 packbf(float lo, float hi) {
    u32 r;
    asm("cvt.rn.bf16x2.f32 %0, %1, %2;" : "=r"(r) : "f"(hi), "f"(lo));
    return r;
}
__device__ __forceinline__ u32 packhf(float lo, float hi) {
    u32 r;
    asm("cvt.rn.f16x2.f32 %0, %1, %2;" : "=r"(r) : "f"(hi), "f"(lo));
    return r;
}
__device__ __forceinline__ float ex2f(float x) {
    float r;
    asm("ex2.approx.f32 %0, %1;" : "=f"(r) : "f"(x));
    return r;
}
__device__ __forceinline__ void mma16816(float* c, const u32* a, const u32* b) {
    asm volatile(
        "mma.sync.aligned.m16n8k16.row.col.f32.bf16.bf16.f32 "
        "{%0,%1,%2,%3}, {%4,%5,%6,%7}, {%8,%9}, {%0,%1,%2,%3};"
        : "+f"(c[0]), "+f"(c[1]), "+f"(c[2]), "+f"(c[3])
        : "r"(a[0]), "r"(a[1]), "r"(a[2]), "r"(a[3]), "r"(b[0]), "r"(b[1]));
}
__device__ __forceinline__ void mma16816h(float* c, const u32* a, const u32* b) {
    asm volatile(
        "mma.sync.aligned.m16n8k16.row.col.f32.f16.f16.f32 "
        "{%0,%1,%2,%3}, {%4,%5,%6,%7}, {%8,%9}, {%0,%1,%2,%3};"
        : "+f"(c[0]), "+f"(c[1]), "+f"(c[2]), "+f"(c[3])
        : "r"(a[0]), "r"(a[1]), "r"(a[2]), "r"(a[3]), "r"(b[0]), "r"(b[1]));
}
__device__ __forceinline__ void ldsm4(u32* r, uint32_t addr) {
    asm volatile("ldmatrix.sync.aligned.m8n8.x4.shared.b16 {%0,%1,%2,%3}, [%4];"
        : "=r"(r[0]), "=r"(r[1]), "=r"(r[2]), "=r"(r[3]) : "r"(addr));
}
__device__ __forceinline__ void ldsm2(u32* r, uint32_t addr) {
    asm volatile("ldmatrix.sync.aligned.m8n8.x2.shared.b16 {%0,%1}, [%2];"
        : "=r"(r[0]), "=r"(r[1]) : "r"(addr));
}
#define CP16(dst, src) asm volatile("cp.async.cg.shared.global [%0], [%1], 16;" :: "r"(dst), "l"(src))
#define CPC()  asm volatile("cp.async.commit_group;")
#define CPW0() asm volatile("cp.async.wait_group 0;")
#define CPW1() asm volatile("cp.async.wait_group 1;")
#define CPW2() asm volatile("cp.async.wait_group 2;")

__device__ __forceinline__ u32 swz128(u32 row, u32 g) { return row * 128u + ((g ^ (row & 7u)) << 4); }
__device__ __forceinline__ u32 swz256(u32 row, u32 g) { return row * 256u + (((g & 8u) | ((g & 7u) ^ (row & 7u))) << 4); }
__device__ __forceinline__ u32 swz512(u32 row, u32 g) { return row * 512u + (((g & 24u) | ((g & 7u) ^ (row & 7u))) << 4); }

// ---------------------------------------------------------------------------
// Kernel 0: weight conversion -> fp16 (32 blocks)
// ---------------------------------------------------------------------------
__global__ void convert_w_kernel(const float* __restrict__ wq, const float* __restrict__ wk,
                                 const float* __restrict__ wv, const float* __restrict__ wsa)
{
    const int p = blockIdx.x & 3;
    const int s8 = blockIdx.x >> 2;
    const float* s = (p == 0) ? wq : (p == 1) ? wk : (p == 2) ? wv : wsa;
    __half* d = (p < 3) ? &g_w[p * DIM * CIN] : g_wsa;
    const int per = DIM * CIN / 8;
    for (int i = threadIdx.x; i < per; i += blockDim.x) {
        int idx = s8 * per + i;
        d[idx] = __float2half(s[idx]);
    }
}

// ---------------------------------------------------------------------------
// Kernel 1: FUSED x-transpose + QKV projections (fp16 HMMA).
// Staging pipelined: 8 chunks of 32 c-rows, 3-buffer ring, prefetch dist 2.
// Smem: A @0 (64K) | B @64K (96K) | XS ring @160K (3 x 16896)
// ---------------------------------------------------------------------------
#define QF_A   0
#define QF_B   65536
#define QF_XS  163840
#define XS_STRIDE 132
#define XS_BUF (32 * XS_STRIDE * 4)     // 16896
#define QF_SMEM (163840 + 3 * XS_BUF)   // 214528

__global__ __launch_bounds__(256, 1) void qkv_fused_kernel(
    const float* __restrict__ x,
    const float* __restrict__ bq, const float* __restrict__ bk, const float* __restrict__ bv)
{
    extern __shared__ char sm[];
    const u32 sb = smem_u32(sm);
    const int tid  = threadIdx.x;
    const int lane = tid & 31;
    const int wid  = tid >> 5;
    const int wm = wid & 3;
    const int wn = wid >> 2;
    const int g  = lane >> 2;
    const int t  = lane & 3;
    const int b  = blockIdx.y;
    const int i0 = blockIdx.x * 128;

    // ---- group 0: all 3 weight matrices + x chunk 0 ----
#pragma unroll
    for (int i = 0; i < 24; i++) {
        int id = tid + i * 256;
        u32 row = (u32)(id >> 5), gg = (u32)(id & 31);
        CP16(sb + QF_B + swz512(row, gg), (const char*)g_w + row * 512 + gg * 16);
    }
#pragma unroll
    for (int i = 0; i < 4; i++) {
        int id = tid + i * 256;
        int r = id >> 5, gg = id & 31;
        CP16(sb + QF_XS + r * (XS_STRIDE * 4) + gg * 16,
             (const char*)&x[(size_t)(b * CIN + r) * HW + i0] + gg * 16);
    }
    CPC();
    // ---- group 1: chunk 1 ----
#pragma unroll
    for (int i = 0; i < 4; i++) {
        int id = tid + i * 256;
        int r = id >> 5, gg = id & 31;
        CP16(sb + QF_XS + XS_BUF + r * (XS_STRIDE * 4) + gg * 16,
             (const char*)&x[(size_t)(b * CIN + 32 + r) * HW + i0] + gg * 16);
    }
    CPC();

    const int tn  = tid & 127;
    const int sel = tid >> 7;            // 0..1
#pragma unroll
    for (int c = 0; c < 8; c++) {
        __syncthreads();   // all reads of chunk c-1 done; safe to issue c+2
        if (c + 2 < 8) {
#pragma unroll
            for (int i = 0; i < 4; i++) {
                int id = tid + i * 256;
                int r = id >> 5, gg = id & 31;
                CP16(sb + QF_XS + ((c + 2) % 3) * XS_BUF + r * (XS_STRIDE * 4) + gg * 16,
                     (const char*)&x[(size_t)(b * CIN + (c + 2) * 32 + r) * HW + i0] + gg * 16);
            }
            CPC();
        }
        if (c < 6) { CPW2(); } else if (c == 6) { CPW1(); } else { CPW0(); }
        __syncthreads();   // chunk c visible to all
        const float* xs = (const float*)(sm + QF_XS + (c % 3) * XS_BUF);
#pragma unroll
        for (int gi = 0; gi < 2; gi++) {
            int gl = sel * 2 + gi;      // 0..3
            u32 w4[4];
#pragma unroll
            for (int s = 0; s < 4; s++) {
                float f0 = xs[(gl * 8 + 2 * s)     * XS_STRIDE + tn];
                float f1 = xs[(gl * 8 + 2 * s + 1) * XS_STRIDE + tn];
                w4[s] = packhf(f0, f1);
            }
            *(uint4*)(sm + QF_A + swz512((u32)tn, (u32)(c * 4 + gl))) = *(uint4*)w4;
        }
    }
    __syncthreads();

    const u32 a_row = wm * 32 + (lane & 15);
    const u32 a_g = (u32)(lane >> 4);
    const u32 b_rl = (u32)(lane & 7);
    const u32 b_g = (u32)((lane >> 3) & 1);

    for (int p = 0; p < 3; p++) {
        const float* bias = (p == 0) ? bq : (p == 1) ? bk : bv;
        const float scl = (p == 0) ? LOG2E : 1.0f;

        float c[2][4][4];
#pragma unroll
        for (int mt = 0; mt < 2; mt++)
#pragma unroll
            for (int nt = 0; nt < 4; nt++)
#pragma unroll
                for (int e = 0; e < 4; e++) c[mt][nt][e] = 0.0f;

#pragma unroll
        for (int kt = 0; kt < 16; kt++) {
            u32 ah2[2][4];
#pragma unroll
            for (int mt = 0; mt < 2; mt++)
                ldsm4(ah2[mt], sb + QF_A + swz512(a_row + mt * 16, a_g + kt * 2));
#pragma unroll
            for (int nt = 0; nt < 4; nt++) {
                u32 bh2[2];
                u32 row = (u32)(p * 64 + wn * 32 + nt * 8) + b_rl;
                ldsm2(bh2, sb + QF_B + swz512(row, b_g + kt * 2));
#pragma unroll
                for (int mt = 0; mt < 2; mt++)
                    mma16816h(c[mt][nt], ah2[mt], bh2);
            }
        }

        if (p < 2) {
            __half* oh = (p == 0) ? g_q : g_k;
#pragma unroll
            for (int mt = 0; mt < 2; mt++)
#pragma unroll
                for (int nt = 0; nt < 4; nt++) {
                    int n = i0 + wm * 32 + mt * 16 + g;
                    int d = wn * 32 + nt * 8 + t * 2;
                    float b0 = bias[d], b1 = bias[d + 1];
                    float v0 = (c[mt][nt][0] + b0) * scl, v1 = (c[mt][nt][1] + b1) * scl;
                    float v2 = (c[mt][nt][2] + b0) * scl, v3 = (c[mt][nt][3] + b1) * scl;
                    size_t o0 = (size_t)(b * HW + n) * DIM + d;
                    size_t o1 = (size_t)(b * HW + n + 8) * DIM + d;
                    *(u32*)&oh[o0] = packhf(v0, v1);
                    *(u32*)&oh[o1] = packhf(v2, v3);
                }
        } else {
            float* ot = (float*)(sm + QF_XS);   // 32KB staging reuse
            __syncthreads();
#pragma unroll
            for (int mt = 0; mt < 2; mt++)
#pragma unroll
                for (int nt = 0; nt < 4; nt++) {
                    int n = wm * 32 + mt * 16 + g;
                    int d = wn * 32 + nt * 8 + t * 2;
                    ot[d * 128 + n]           = c[mt][nt][0];
                    ot[(d + 1) * 128 + n]     = c[mt][nt][1];
                    ot[d * 128 + n + 8]       = c[mt][nt][2];
                    ot[(d + 1) * 128 + n + 8] = c[mt][nt][3];
                }
            __syncthreads();
            int d  = tid >> 2;
            int ns = (tid & 3) * 32;
            float bvv = bias[d];
            u32 hh[16];
#pragma unroll
            for (int j = 0; j < 32; j += 2) {
                float v0 = ot[d * 128 + ns + j] + bvv;
                float v1 = ot[d * 128 + ns + j + 1] + bvv;
                hh[j >> 1] = packbf(v0, v1);
            }
            size_t base = (size_t)(b * DIM + d) * HW + i0 + ns;
#pragma unroll
            for (int q4 = 0; q4 < 4; q4++)
                *(uint4*)&g_vth[base + q4 * 8] = *(uint4*)&hh[q4 * 4];
        }
    }
}

// ---------------------------------------------------------------------------
// Kernel 2: HMMA flash attention, PV1 rotated across the tile boundary so
// every exp burst has fresh MMAs queued on the tensor pipe.
// ---------------------------------------------------------------------------
#define ATT_BUF0   16384
#define ATT_BUFSZ  32768
#define SM_TOTAL   81920

__device__ __forceinline__ void load_kv(u32 sb, u32 bufbase, int b, int j0, int tid)
{
    const char* kh = (const char*)&g_k[(size_t)(b * HW + j0) * DIM];
#pragma unroll
    for (int i = 0; i < 2; i++) {
        int id = tid + i * 512, row = id >> 3, g = id & 7;
        CP16(sb + bufbase + swz128(row, g), kh + row * 128 + g * 16);
    }
    const char* vh = (const char*)&g_vth[(size_t)b * DIM * HW + j0];
#pragma unroll
    for (int i = 0; i < 2; i++) {
        int id = tid + i * 512, d = id >> 4, g = id & 15;
        CP16(sb + bufbase + 16384 + swz256(d, g), vh + d * (HW * 2) + g * 16);
    }
}

__global__ __launch_bounds__(512, 1) void attn_kernel()
{
    extern __shared__ char sm[];
    const u32 sb = smem_u32(sm);
    const int tid  = threadIdx.x;
    const int lane = tid & 31;
    const int wid  = tid >> 5;
    const int wm = wid & 7;
    const int wn = wid >> 3;
    const int b  = blockIdx.y;
    const int i0 = blockIdx.x * 128;
    const int g  = lane >> 2;
    const int t  = lane & 3;

    {
        const char* qh = (const char*)&g_q[(size_t)(b * HW + i0) * DIM];
#pragma unroll
        for (int i = 0; i < 2; i++) {
            int id = tid + i * 512, row = id >> 3, gg = id & 7;
            CP16(sb + swz128(row, gg), qh + row * 128 + gg * 16);
        }
        load_kv(sb, ATT_BUF0, b, 0, tid);
        CPC(); CPW0();
        __syncthreads();
    }

    u32 qf[4][4];
    {
        const u32 q_row  = wm * 16 + (lane & 15);
        const u32 q_gsel = (u32)(lane >> 4);
#pragma unroll
        for (int kt = 0; kt < 4; kt++)
            ldsm4(qf[kt], sb + swz128(q_row, q_gsel + kt * 2));
    }

    float oc[8][4];
    float lsum[2];
    lsum[0] = 0.0f; lsum[1] = 0.0f;
#pragma unroll
    for (int dnt = 0; dnt < 8; dnt++)
#pragma unroll
        for (int e = 0; e < 4; e++) oc[dnt][e] = 0.0f;

    const u32 b_ro = (u32)(((lane >> 4) << 3) + (lane & 7));
    const u32 b_gg = (u32)((lane >> 3) & 1);

    float sc[4][4];
    u32 ph0[2][4], ph1[2][4];

    // ---- prologue: prefetch tile 1, compute tile 0 minus PV1 ----
    load_kv(sb, ATT_BUF0 + ATT_BUFSZ, b, 128, tid);
    CPC();

#define S_HALF(BUF, HOFF)                                                      \
    {                                                                          \
        _Pragma("unroll")                                                      \
        for (int nt = 0; nt < 4; nt++)                                         \
            _Pragma("unroll")                                                  \
            for (int e = 0; e < 4; e++) sc[nt][e] = 0.0f;                      \
        _Pragma("unroll")                                                      \
        for (int kt = 0; kt < 4; kt++)                                         \
            _Pragma("unroll")                                                  \
            for (int ntp = 0; ntp < 2; ntp++) {                                \
                u32 bh[4];                                                     \
                u32 ro = (u32)(wn * 64 + (HOFF) + ntp * 16) + b_ro;            \
                ldsm4(bh, sb + (BUF) + swz128(ro, b_gg + kt * 2));             \
                mma16816h(sc[ntp * 2 + 0], qf[kt], bh + 0);                    \
                mma16816h(sc[ntp * 2 + 1], qf[kt], bh + 2);                    \
            }                                                                  \
    }

#define EXP_HALF(PH)                                                           \
    {                                                                          \
        _Pragma("unroll")                                                      \
        for (int jj = 0; jj < 2; jj++)                                         \
            _Pragma("unroll")                                                  \
            for (int h = 0; h < 2; h++) {                                      \
                int nt = jj * 2 + h;                                           \
                float e0 = ex2f(sc[nt][0]);                                    \
                float e1 = ex2f(sc[nt][1]);                                    \
                float e2 = ex2f(sc[nt][2]);                                    \
                float e3 = ex2f(sc[nt][3]);                                    \
                lsum[0] += e0 + e1;                                            \
                lsum[1] += e2 + e3;                                            \
                (PH)[jj][h * 2 + 0] = packbf(e0, e1);                          \
                (PH)[jj][h * 2 + 1] = packbf(e2, e3);                          \
            }                                                                  \
    }

#define PV_HALF(BUF, PH, JBASE)                                                \
    {                                                                          \
        _Pragma("unroll")                                                      \
        for (int jj = 0; jj < 2; jj++)                                         \
            _Pragma("unroll")                                                  \
            for (int dntp = 0; dntp < 4; dntp++) {                             \
                u32 bvh[4];                                                    \
                u32 ro = (u32)(dntp * 16) + b_ro;                              \
                u32 gg = (u32)(wn * 8 + ((JBASE) + jj) * 2) + b_gg;            \
                ldsm4(bvh, sb + (BUF) + 16384 + swz256(ro, gg));               \
                mma16816((oc)[dntp * 2 + 0], (PH)[jj], bvh + 0);               \
                mma16816((oc)[dntp * 2 + 1], (PH)[jj], bvh + 2);               \
            }                                                                  \
    }

    // tile 0 body (PV1 deferred)
    S_HALF(ATT_BUF0, 0)
    EXP_HALF(ph0)
    S_HALF(ATT_BUF0, 32)
    PV_HALF(ATT_BUF0, ph0, 0)
    EXP_HALF(ph1)

    for (int jt = 1; jt < HW / 128; jt++) {
        CPW0();
        __syncthreads();
        const u32 pbuf = ATT_BUF0 + (u32)((jt - 1) & 1) * ATT_BUFSZ;
        PV_HALF(pbuf, ph1, 2)          // deferred PV1 of tile jt-1
        __syncthreads();               // PV1 reads done before overwrite
        if (jt + 1 < HW / 128) {
            load_kv(sb, ATT_BUF0 + (u32)((jt + 1) & 1) * ATT_BUFSZ, b, (jt + 1) * 128, tid);
            CPC();
        }
        const u32 buf = ATT_BUF0 + (u32)(jt & 1) * ATT_BUFSZ;
        S_HALF(buf, 0)
        EXP_HALF(ph0)
        S_HALF(buf, 32)
        PV_HALF(buf, ph0, 0)
        EXP_HALF(ph1)
    }
    // final deferred PV1 (tile 31, buffer (31)&1)
    {
        const u32 pbuf = ATT_BUF0 + (u32)((HW / 128 - 1) & 1) * ATT_BUFSZ;
        PV_HALF(pbuf, ph1, 2)
    }
    __syncthreads();

    // ---- epilogue ----
    float* lp = (float*)(sm + 65536);
#pragma unroll
    for (int r = 0; r < 2; r++) {
        float v = lsum[r];
        v += __shfl_xor_sync(0xffffffffu, v, 1);
        v += __shfl_xor_sync(0xffffffffu, v, 2);
        if (t == 0) lp[wn * 128 + wm * 16 + r * 8 + g] = v;
    }
    float* op = (float*)(sm + wn * 32768);
#pragma unroll
    for (int dnt = 0; dnt < 8; dnt++) {
        int r0 = wm * 16 + g;
        int c = dnt * 8 + t * 2;
        *(float2*)&op[r0 * 64 + c]       = make_float2(oc[dnt][0], oc[dnt][1]);
        *(float2*)&op[(r0 + 8) * 64 + c] = make_float2(oc[dnt][2], oc[dnt][3]);
    }
    __syncthreads();

    float* o0 = (float*)sm;
    float* o1 = (float*)(sm + 32768);
    float* lpf = (float*)(sm + 65536);
#pragma unroll
    for (int i = 0; i < 4; i++) {
        int idx = tid + i * 512;
        int row = idx >> 4, c4 = (idx & 15) * 4;
        float invl = 1.0f / (lpf[row] + lpf[128 + row]);
        float4 a = *(float4*)&o0[row * 64 + c4];
        float4 bb = *(float4*)&o1[row * 64 + c4];
        float v0 = (a.x + bb.x) * invl;
        float v1 = (a.y + bb.y) * invl;
        float v2 = (a.z + bb.z) * invl;
        float v3 = (a.w + bb.w) * invl;
        size_t off = (size_t)(b * HW + i0 + row) * DIM + c4;
        *(uint2*)&g_sa[off] = make_uint2(packhf(v0, v1), packhf(v2, v3));
    }
}

// ---------------------------------------------------------------------------
// Kernel 3: output projection, x/bias loads hoisted to kernel entry for MLP.
// ---------------------------------------------------------------------------
#define PROJ_SMEM 24576

__global__ __launch_bounds__(256) void proj_mma_kernel(
    const float* __restrict__ x,
    const float* __restrict__ bsa,
    const float* __restrict__ gamma,
    float* __restrict__ out)
{
    extern __shared__ char sm[];
    const u32 sb = smem_u32(sm);
    const int tid  = threadIdx.x;
    const int lane = tid & 31;
    const int wid  = tid >> 5;
    const int wm = wid & 3;
    const int wn = wid >> 2;
    const int g  = lane >> 2;
    const int t  = lane & 3;
    const int b  = blockIdx.z;
    const int c0 = blockIdx.y * 64;
    const int n0 = blockIdx.x * 128;

    // ---- hoisted epilogue inputs (16 independent LDG.64 + bias + gamma) ----
    const int cg = c0 + wm * 16 + g;
    float2 xva[8], xvb[8];
    size_t offs[8];
#pragma unroll
    for (int nt = 0; nt < 8; nt++) {
        int n = n0 + wn * 64 + nt * 8 + t * 2;
        offs[nt] = ((size_t)(b * CIN) + cg) * HW + n;
        xva[nt] = *(const float2*)&x[offs[nt]];
        xvb[nt] = *(const float2*)&x[offs[nt] + (size_t)8 * HW];
    }
    const float b0 = bsa[cg], b1 = bsa[cg + 8];
    const float gm = gamma[0];

    {
        const char* ah = (const char*)&g_wsa[(size_t)c0 * DIM];
        const char* bh = (const char*)&g_sa[(size_t)(b * HW + n0) * DIM];
#pragma unroll
        for (int i = 0; i < 2; i++) {
            int id = tid + i * 256;
            u32 row = (u32)(id >> 3), gg = (u32)(id & 7);
            CP16(sb + swz128(row, gg), ah + row * 128 + gg * 16);
        }
#pragma unroll
        for (int i = 0; i < 4; i++) {
            int id = tid + i * 256;
            u32 row = (u32)(id >> 3), gg = (u32)(id & 7);
            CP16(sb + 8192 + swz128(row, gg), bh + row * 128 + gg * 16);
        }
        CPC(); CPW0();
        __syncthreads();
    }

    float c[8][4];
#pragma unroll
    for (int nt = 0; nt < 8; nt++)
#pragma unroll
        for (int e = 0; e < 4; e++) c[nt][e] = 0.0f;

    const u32 a_row = wm * 16 + (lane & 15);
    const u32 a_g = (u32)(lane >> 4);
    const u32 b_row = wn * 64 + (lane & 7);
    const u32 b_g = (u32)((lane >> 3) & 1);

#pragma unroll
    for (int kt = 0; kt < 4; kt++) {
        u32 ah2[4];
        ldsm4(ah2, sb + swz128(a_row, a_g + kt * 2));
#pragma unroll
        for (int nt = 0; nt < 8; nt++) {
            u32 bh2[2];
            ldsm2(bh2, sb + 8192 + swz128(b_row + nt * 8, b_g + kt * 2));
            mma16816h(c[nt], ah2, bh2);
        }
    }

#pragma unroll
    for (int nt = 0; nt < 8; nt++) {
        float2 o0, o1;
        o0.x = gm * (c[nt][0] + b0) + xva[nt].x;
        o0.y = gm * (c[nt][1] + b0) + xva[nt].y;
        o1.x = gm * (c[nt][2] + b1) + xvb[nt].x;
        o1.y = gm * (c[nt][3] + b1) + xvb[nt].y;
        *(float2*)&out[offs[nt]] = o0;
        *(float2*)&out[offs[nt] + (size_t)8 * HW] = o1;
    }
}

// ---------------------------------------------------------------------------
extern "C" void kernel_launch(void* const* d_in, const int* in_sizes, int n_in,
                              void* d_out, int out_size)
{
    const float* x     = (const float*)d_in[0];
    const float* wq    = (const float*)d_in[1];
    const float* bq    = (const float*)d_in[2];
    const float* wk    = (const float*)d_in[3];
    const float* bk    = (const float*)d_in[4];
    const float* wv    = (const float*)d_in[5];
    const float* bv    = (const float*)d_in[6];
    const float* wsa   = (const float*)d_in[7];
    const float* bsa   = (const float*)d_in[8];
    const float* gamma = (const float*)d_in[9];
    float* out = (float*)d_out;

    cudaFuncSetAttribute(attn_kernel, cudaFuncAttributeMaxDynamicSharedMemorySize, SM_TOTAL);
    cudaFuncSetAttribute(qkv_fused_kernel, cudaFuncAttributeMaxDynamicSharedMemorySize, QF_SMEM);
    cudaFuncSetAttribute(proj_mma_kernel, cudaFuncAttributeMaxDynamicSharedMemorySize, PROJ_SMEM);

    convert_w_kernel<<<32, 256>>>(wq, wk, wv, wsa);
    qkv_fused_kernel<<<dim3(HW / 128, BATCH), 256, QF_SMEM>>>(x, bq, bk, bv);
    attn_kernel<<<dim3(HW / 128, BATCH), 512, SM_TOTAL>>>();
    proj_mma_kernel<<<dim3(HW / 128, CIN / 64, BATCH), 256, PROJ_SMEM>>>(x, bsa, gamma, out);
}

// round 17
// speedup vs baseline: 1.0506x; 1.0506x over previous
#include <cuda_runtime.h>
#include <cuda_bf16.h>
#include <cuda_fp16.h>
#include <math.h>
#include <stdint.h>
#include <string.h>

#define BATCH 4
#define CIN   256
#define HW    4096
#define DIM   64
#define LOG2E 1.4426950408889634f

typedef unsigned int u32;
typedef unsigned long long u64;

// ---------------------------------------------------------------------------
// Device scratch
// ---------------------------------------------------------------------------
__device__ __half g_w[3 * DIM * CIN];              // wq|wk|wv stacked [192][256]
__device__ __half g_wsa[CIN * DIM];
__device__ __half g_q[BATCH * HW * DIM];           // pre-scaled by log2(e)
__device__ __half g_k[BATCH * HW * DIM];
__device__ __nv_bfloat16 g_vth[BATCH * DIM * HW];  // [b][d][j] bf16
__device__ __half g_sa[BATCH * HW * DIM];          // attention out [b][n][d]

// ---------------------------------------------------------------------------
// Helpers
// ---------------------------------------------------------------------------
__device__ __forceinline__ uint32_t smem_u32(const void* p) {
    uint32_t a;
    asm("{ .reg .u64 t; cvta.to.shared.u64 t, %1; cvt.u32.u64 %0, t; }" : "=r"(a) : "l"(p));
    return a;
}
__device__ __forceinline__ u32 packbf(float lo, float hi) {
    u32 r;
    asm("cvt.rn.bf16x2.f32 %0, %1, %2;" : "=r"(r) : "f"(hi), "f"(lo));
    return r;
}
__device__ __forceinline__ u32 packhf(float lo, float hi) {
    u32 r;
    asm("cvt.rn.f16x2.f32 %0, %1, %2;" : "=r"(r) : "f"(hi), "f"(lo));
    return r;
}
__device__ __forceinline__ float ex2f(float x) {
    float r;
    asm("ex2.approx.f32 %0, %1;" : "=f"(r) : "f"(x));
    return r;
}
__device__ __forceinline__ void mma16816(float* c, const u32* a, const u32* b) {
    asm volatile(
        "mma.sync.aligned.m16n8k16.row.col.f32.bf16.bf16.f32 "
        "{%0,%1,%2,%3}, {%4,%5,%6,%7}, {%8,%9}, {%0,%1,%2,%3};"
        : "+f"(c[0]), "+f"(c[1]), "+f"(c[2]), "+f"(c[3])
        : "r"(a[0]), "r"(a[1]), "r"(a[2]), "r"(a[3]), "r"(b[0]), "r"(b[1]));
}
__device__ __forceinline__ void mma16816h(float* c, const u32* a, const u32* b) {
    asm volatile(
        "mma.sync.aligned.m16n8k16.row.col.f32.f16.f16.f32 "
        "{%0,%1,%2,%3}, {%4,%5,%6,%7}, {%8,%9}, {%0,%1,%2,%3};"
        : "+f"(c[0]), "+f"(c[1]), "+f"(c[2]), "+f"(c[3])
        : "r"(a[0]), "r"(a[1]), "r"(a[2]), "r"(a[3]), "r"(b[0]), "r"(b[1]));
}
__device__ __forceinline__ void ldsm4(u32* r, uint32_t addr) {
    asm volatile("ldmatrix.sync.aligned.m8n8.x4.shared.b16 {%0,%1,%2,%3}, [%4];"
        : "=r"(r[0]), "=r"(r[1]), "=r"(r[2]), "=r"(r[3]) : "r"(addr));
}
__device__ __forceinline__ void ldsm2(u32* r, uint32_t addr) {
    asm volatile("ldmatrix.sync.aligned.m8n8.x2.shared.b16 {%0,%1}, [%2];"
        : "=r"(r[0]), "=r"(r[1]) : "r"(addr));
}
#define CP16(dst, src) asm volatile("cp.async.cg.shared.global [%0], [%1], 16;" :: "r"(dst), "l"(src))
#define CPC()  asm volatile("cp.async.commit_group;")
#define CPW0() asm volatile("cp.async.wait_group 0;")

__device__ __forceinline__ u32 swz128(u32 row, u32 g) { return row * 128u + ((g ^ (row & 7u)) << 4); }
__device__ __forceinline__ u32 swz256(u32 row, u32 g) { return row * 256u + (((g & 8u) | ((g & 7u) ^ (row & 7u))) << 4); }
__device__ __forceinline__ u32 swz512(u32 row, u32 g) { return row * 512u + (((g & 24u) | ((g & 7u) ^ (row & 7u))) << 4); }

// ---------------------------------------------------------------------------
// Kernel 0: weight conversion -> fp16 (32 blocks)
// ---------------------------------------------------------------------------
__global__ void convert_w_kernel(const float* __restrict__ wq, const float* __restrict__ wk,
                                 const float* __restrict__ wv, const float* __restrict__ wsa)
{
    const int p = blockIdx.x & 3;
    const int s8 = blockIdx.x >> 2;
    const float* s = (p == 0) ? wq : (p == 1) ? wk : (p == 2) ? wv : wsa;
    __half* d = (p < 3) ? &g_w[p * DIM * CIN] : g_wsa;
    const int per = DIM * CIN / 8;
    for (int i = threadIdx.x; i < per; i += blockDim.x) {
        int idx = s8 * per + i;
        d[idx] = __float2half(s[idx]);
    }
}

// ---------------------------------------------------------------------------
// Kernel 1: FUSED x-transpose + QKV projections (fp16 HMMA). R15 version.
// Smem: A @0 (64K) | B @64K (96K) | XS @160K (fp32 staging, 33.8K)
// ---------------------------------------------------------------------------
#define QF_A   0
#define QF_B   65536
#define QF_XS  163840
#define QF_SMEM 197632
#define XS_STRIDE 132

__global__ __launch_bounds__(256, 1) void qkv_fused_kernel(
    const float* __restrict__ x,
    const float* __restrict__ bq, const float* __restrict__ bk, const float* __restrict__ bv)
{
    extern __shared__ char sm[];
    const u32 sb = smem_u32(sm);
    const int tid  = threadIdx.x;
    const int lane = tid & 31;
    const int wid  = tid >> 5;
    const int wm = wid & 3;
    const int wn = wid >> 2;
    const int g  = lane >> 2;
    const int t  = lane & 3;
    const int b  = blockIdx.y;
    const int i0 = blockIdx.x * 128;

#pragma unroll
    for (int i = 0; i < 24; i++) {
        int id = tid + i * 256;
        u32 row = (u32)(id >> 5), gg = (u32)(id & 31);
        CP16(sb + QF_B + swz512(row, gg), (const char*)g_w + row * 512 + gg * 16);
    }
    CPC();

    float* xs = (float*)(sm + QF_XS);
    const int tn  = (lane) + ((tid >> 5) & 3) * 32;
    const int glh = (tid >> 7) * 4;
    for (int kc = 0; kc < 4; kc++) {
        CPW0();
        __syncthreads();
#pragma unroll
        for (int i = 0; i < 8; i++) {
            int id = tid + i * 256;
            int r = id >> 5, gg = id & 31;
            CP16(sb + QF_XS + r * (XS_STRIDE * 4) + gg * 16,
                 (const char*)&x[(size_t)(b * CIN + kc * 64 + r) * HW + i0] + gg * 16);
        }
        CPC(); CPW0();
        __syncthreads();
#pragma unroll
        for (int gi = 0; gi < 4; gi++) {
            int gl = glh + gi;
            u32 w4[4];
#pragma unroll
            for (int s = 0; s < 4; s++) {
                float f0 = xs[(gl * 8 + 2 * s)     * XS_STRIDE + tn];
                float f1 = xs[(gl * 8 + 2 * s + 1) * XS_STRIDE + tn];
                w4[s] = packhf(f0, f1);
            }
            *(uint4*)(sm + QF_A + swz512((u32)tn, (u32)(kc * 8 + gl))) = *(uint4*)w4;
        }
    }
    __syncthreads();

    const u32 a_row = wm * 32 + (lane & 15);
    const u32 a_g = (u32)(lane >> 4);
    const u32 b_rl = (u32)(lane & 7);
    const u32 b_g = (u32)((lane >> 3) & 1);

    for (int p = 0; p < 3; p++) {
        const float* bias = (p == 0) ? bq : (p == 1) ? bk : bv;
        const float scl = (p == 0) ? LOG2E : 1.0f;

        float c[2][4][4];
#pragma unroll
        for (int mt = 0; mt < 2; mt++)
#pragma unroll
            for (int nt = 0; nt < 4; nt++)
#pragma unroll
                for (int e = 0; e < 4; e++) c[mt][nt][e] = 0.0f;

#pragma unroll
        for (int kt = 0; kt < 16; kt++) {
            u32 ah2[2][4];
#pragma unroll
            for (int mt = 0; mt < 2; mt++)
                ldsm4(ah2[mt], sb + QF_A + swz512(a_row + mt * 16, a_g + kt * 2));
#pragma unroll
            for (int nt = 0; nt < 4; nt++) {
                u32 bh2[2];
                u32 row = (u32)(p * 64 + wn * 32 + nt * 8) + b_rl;
                ldsm2(bh2, sb + QF_B + swz512(row, b_g + kt * 2));
#pragma unroll
                for (int mt = 0; mt < 2; mt++)
                    mma16816h(c[mt][nt], ah2[mt], bh2);
            }
        }

        if (p < 2) {
            __half* oh = (p == 0) ? g_q : g_k;
#pragma unroll
            for (int mt = 0; mt < 2; mt++)
#pragma unroll
                for (int nt = 0; nt < 4; nt++) {
                    int n = i0 + wm * 32 + mt * 16 + g;
                    int d = wn * 32 + nt * 8 + t * 2;
                    float b0 = bias[d], b1 = bias[d + 1];
                    float v0 = (c[mt][nt][0] + b0) * scl, v1 = (c[mt][nt][1] + b1) * scl;
                    float v2 = (c[mt][nt][2] + b0) * scl, v3 = (c[mt][nt][3] + b1) * scl;
                    size_t o0 = (size_t)(b * HW + n) * DIM + d;
                    size_t o1 = (size_t)(b * HW + n + 8) * DIM + d;
                    *(u32*)&oh[o0] = packhf(v0, v1);
                    *(u32*)&oh[o1] = packhf(v2, v3);
                }
        } else {
            float* ot = (float*)(sm + QF_XS);
            __syncthreads();
#pragma unroll
            for (int mt = 0; mt < 2; mt++)
#pragma unroll
                for (int nt = 0; nt < 4; nt++) {
                    int n = wm * 32 + mt * 16 + g;
                    int d = wn * 32 + nt * 8 + t * 2;
                    ot[d * 128 + n]           = c[mt][nt][0];
                    ot[(d + 1) * 128 + n]     = c[mt][nt][1];
                    ot[d * 128 + n + 8]       = c[mt][nt][2];
                    ot[(d + 1) * 128 + n + 8] = c[mt][nt][3];
                }
            __syncthreads();
            int d  = tid >> 2;
            int ns = (tid & 3) * 32;
            float bvv = bias[d];
            u32 hh[16];
#pragma unroll
            for (int j = 0; j < 32; j += 2) {
                float v0 = ot[d * 128 + ns + j] + bvv;
                float v1 = ot[d * 128 + ns + j + 1] + bvv;
                hh[j >> 1] = packbf(v0, v1);
            }
            size_t base = (size_t)(b * DIM + d) * HW + i0 + ns;
#pragma unroll
            for (int q4 = 0; q4 < 4; q4++)
                *(uint4*)&g_vth[base + q4 * 8] = *(uint4*)&hh[q4 * 4];
        }
    }
}

// ---------------------------------------------------------------------------
// Kernel 2: HMMA flash attention (R15/R14 proven mainloop; lsum split 4-way).
// ---------------------------------------------------------------------------
#define ATT_BUF0   16384
#define ATT_BUFSZ  32768
#define SM_TOTAL   81920

__device__ __forceinline__ void load_kv(u32 sb, u32 bufbase, int b, int j0, int tid)
{
    const char* kh = (const char*)&g_k[(size_t)(b * HW + j0) * DIM];
#pragma unroll
    for (int i = 0; i < 2; i++) {
        int id = tid + i * 512, row = id >> 3, g = id & 7;
        CP16(sb + bufbase + swz128(row, g), kh + row * 128 + g * 16);
    }
    const char* vh = (const char*)&g_vth[(size_t)b * DIM * HW + j0];
#pragma unroll
    for (int i = 0; i < 2; i++) {
        int id = tid + i * 512, d = id >> 4, g = id & 15;
        CP16(sb + bufbase + 16384 + swz256(d, g), vh + d * (HW * 2) + g * 16);
    }
}

__global__ __launch_bounds__(512, 1) void attn_kernel()
{
    extern __shared__ char sm[];
    const u32 sb = smem_u32(sm);
    const int tid  = threadIdx.x;
    const int lane = tid & 31;
    const int wid  = tid >> 5;
    const int wm = wid & 7;
    const int wn = wid >> 3;
    const int b  = blockIdx.y;
    const int i0 = blockIdx.x * 128;
    const int g  = lane >> 2;
    const int t  = lane & 3;

    {
        const char* qh = (const char*)&g_q[(size_t)(b * HW + i0) * DIM];
#pragma unroll
        for (int i = 0; i < 2; i++) {
            int id = tid + i * 512, row = id >> 3, gg = id & 7;
            CP16(sb + swz128(row, gg), qh + row * 128 + gg * 16);
        }
        load_kv(sb, ATT_BUF0, b, 0, tid);
        CPC(); CPW0();
        __syncthreads();
    }

    u32 qf[4][4];
    {
        const u32 q_row  = wm * 16 + (lane & 15);
        const u32 q_gsel = (u32)(lane >> 4);
#pragma unroll
        for (int kt = 0; kt < 4; kt++)
            ldsm4(qf[kt], sb + swz128(q_row, q_gsel + kt * 2));
    }

    float oc[8][4];
    float ls[4];  // 4 independent row-sum accumulators: [r0a, r1a, r0b, r1b]
    ls[0] = 0.0f; ls[1] = 0.0f; ls[2] = 0.0f; ls[3] = 0.0f;
#pragma unroll
    for (int dnt = 0; dnt < 8; dnt++)
#pragma unroll
        for (int e = 0; e < 4; e++) oc[dnt][e] = 0.0f;

    const u32 b_ro = (u32)(((lane >> 4) << 3) + (lane & 7));
    const u32 b_gg = (u32)((lane >> 3) & 1);

    for (int jt = 0; jt < HW / 128; jt++) {
        CPW0();
        __syncthreads();
        const u32 buf = ATT_BUF0 + (u32)(jt & 1) * ATT_BUFSZ;
        if (jt + 1 < HW / 128) {
            load_kv(sb, ATT_BUF0 + (u32)((jt + 1) & 1) * ATT_BUFSZ, b, (jt + 1) * 128, tid);
            CPC();
        }

        float sc[4][4];
        u32 ph0[2][4], ph1[2][4];

        // ---- S half 0 ----
#pragma unroll
        for (int nt = 0; nt < 4; nt++)
#pragma unroll
            for (int e = 0; e < 4; e++) sc[nt][e] = 0.0f;
#pragma unroll
        for (int kt = 0; kt < 4; kt++)
#pragma unroll
            for (int ntp = 0; ntp < 2; ntp++) {
                u32 bh[4];
                u32 ro = (u32)(wn * 64 + ntp * 16) + b_ro;
                ldsm4(bh, sb + buf + swz128(ro, b_gg + kt * 2));
                mma16816h(sc[ntp * 2 + 0], qf[kt], bh + 0);
                mma16816h(sc[ntp * 2 + 1], qf[kt], bh + 2);
            }

        // ---- exp half 0 ----
#pragma unroll
        for (int jj = 0; jj < 2; jj++)
#pragma unroll
            for (int h = 0; h < 2; h++) {
                int nt = jj * 2 + h;
                float e0 = ex2f(sc[nt][0]);
                float e1 = ex2f(sc[nt][1]);
                float e2 = ex2f(sc[nt][2]);
                float e3 = ex2f(sc[nt][3]);
                ls[0] += e0; ls[2] += e1;
                ls[1] += e2; ls[3] += e3;
                ph0[jj][h * 2 + 0] = packbf(e0, e1);
                ph0[jj][h * 2 + 1] = packbf(e2, e3);
            }

        // ---- S half 1 ----
#pragma unroll
        for (int nt = 0; nt < 4; nt++)
#pragma unroll
            for (int e = 0; e < 4; e++) sc[nt][e] = 0.0f;
#pragma unroll
        for (int kt = 0; kt < 4; kt++)
#pragma unroll
            for (int ntp = 0; ntp < 2; ntp++) {
                u32 bh[4];
                u32 ro = (u32)(wn * 64 + 32 + ntp * 16) + b_ro;
                ldsm4(bh, sb + buf + swz128(ro, b_gg + kt * 2));
                mma16816h(sc[ntp * 2 + 0], qf[kt], bh + 0);
                mma16816h(sc[ntp * 2 + 1], qf[kt], bh + 2);
            }

        // ---- PV half 0 ----
#pragma unroll
        for (int jj = 0; jj < 2; jj++) {
#pragma unroll
            for (int dntp = 0; dntp < 4; dntp++) {
                u32 bvh[4];
                u32 ro = (u32)(dntp * 16) + b_ro;
                u32 gg = (u32)(wn * 8 + jj * 2) + b_gg;
                ldsm4(bvh, sb + buf + 16384 + swz256(ro, gg));
                mma16816(oc[dntp * 2 + 0], ph0[jj], bvh + 0);
                mma16816(oc[dntp * 2 + 1], ph0[jj], bvh + 2);
            }
        }

        // ---- exp half 1 ----
#pragma unroll
        for (int jj = 0; jj < 2; jj++)
#pragma unroll
            for (int h = 0; h < 2; h++) {
                int nt = jj * 2 + h;
                float e0 = ex2f(sc[nt][0]);
                float e1 = ex2f(sc[nt][1]);
                float e2 = ex2f(sc[nt][2]);
                float e3 = ex2f(sc[nt][3]);
                ls[0] += e0; ls[2] += e1;
                ls[1] += e2; ls[3] += e3;
                ph1[jj][h * 2 + 0] = packbf(e0, e1);
                ph1[jj][h * 2 + 1] = packbf(e2, e3);
            }

        // ---- PV half 1 ----
#pragma unroll
        for (int jj = 0; jj < 2; jj++) {
#pragma unroll
            for (int dntp = 0; dntp < 4; dntp++) {
                u32 bvh[4];
                u32 ro = (u32)(dntp * 16) + b_ro;
                u32 gg = (u32)(wn * 8 + (2 + jj) * 2) + b_gg;
                ldsm4(bvh, sb + buf + 16384 + swz256(ro, gg));
                mma16816(oc[dntp * 2 + 0], ph1[jj], bvh + 0);
                mma16816(oc[dntp * 2 + 1], ph1[jj], bvh + 2);
            }
        }
    }
    __syncthreads();

    // ---- epilogue ----
    float lsum[2];
    lsum[0] = ls[0] + ls[2];
    lsum[1] = ls[1] + ls[3];
    float* lp = (float*)(sm + 65536);
#pragma unroll
    for (int r = 0; r < 2; r++) {
        float v = lsum[r];
        v += __shfl_xor_sync(0xffffffffu, v, 1);
        v += __shfl_xor_sync(0xffffffffu, v, 2);
        if (t == 0) lp[wn * 128 + wm * 16 + r * 8 + g] = v;
    }
    float* op = (float*)(sm + wn * 32768);
#pragma unroll
    for (int dnt = 0; dnt < 8; dnt++) {
        int r0 = wm * 16 + g;
        int c = dnt * 8 + t * 2;
        *(float2*)&op[r0 * 64 + c]       = make_float2(oc[dnt][0], oc[dnt][1]);
        *(float2*)&op[(r0 + 8) * 64 + c] = make_float2(oc[dnt][2], oc[dnt][3]);
    }
    __syncthreads();

    float* o0 = (float*)sm;
    float* o1 = (float*)(sm + 32768);
    float* lpf = (float*)(sm + 65536);
#pragma unroll
    for (int i = 0; i < 4; i++) {
        int idx = tid + i * 512;
        int row = idx >> 4, c4 = (idx & 15) * 4;
        float invl = 1.0f / (lpf[row] + lpf[128 + row]);
        float4 a = *(float4*)&o0[row * 64 + c4];
        float4 bb = *(float4*)&o1[row * 64 + c4];
        float v0 = (a.x + bb.x) * invl;
        float v1 = (a.y + bb.y) * invl;
        float v2 = (a.z + bb.z) * invl;
        float v3 = (a.w + bb.w) * invl;
        size_t off = (size_t)(b * HW + i0 + row) * DIM + c4;
        *(uint2*)&g_sa[off] = make_uint2(packhf(v0, v1), packhf(v2, v3));
    }
}

// ---------------------------------------------------------------------------
// Kernel 3: output projection (R16 version: hoisted epilogue loads, kept).
// ---------------------------------------------------------------------------
#define PROJ_SMEM 24576

__global__ __launch_bounds__(256) void proj_mma_kernel(
    const float* __restrict__ x,
    const float* __restrict__ bsa,
    const float* __restrict__ gamma,
    float* __restrict__ out)
{
    extern __shared__ char sm[];
    const u32 sb = smem_u32(sm);
    const int tid  = threadIdx.x;
    const int lane = tid & 31;
    const int wid  = tid >> 5;
    const int wm = wid & 3;
    const int wn = wid >> 2;
    const int g  = lane >> 2;
    const int t  = lane & 3;
    const int b  = blockIdx.z;
    const int c0 = blockIdx.y * 64;
    const int n0 = blockIdx.x * 128;

    // hoisted epilogue inputs
    const int cg = c0 + wm * 16 + g;
    float2 xva[8], xvb[8];
    size_t offs[8];
#pragma unroll
    for (int nt = 0; nt < 8; nt++) {
        int n = n0 + wn * 64 + nt * 8 + t * 2;
        offs[nt] = ((size_t)(b * CIN) + cg) * HW + n;
        xva[nt] = *(const float2*)&x[offs[nt]];
        xvb[nt] = *(const float2*)&x[offs[nt] + (size_t)8 * HW];
    }
    const float b0 = bsa[cg], b1 = bsa[cg + 8];
    const float gm = gamma[0];

    {
        const char* ah = (const char*)&g_wsa[(size_t)c0 * DIM];
        const char* bh = (const char*)&g_sa[(size_t)(b * HW + n0) * DIM];
#pragma unroll
        for (int i = 0; i < 2; i++) {
            int id = tid + i * 256;
            u32 row = (u32)(id >> 3), gg = (u32)(id & 7);
            CP16(sb + swz128(row, gg), ah + row * 128 + gg * 16);
        }
#pragma unroll
        for (int i = 0; i < 4; i++) {
            int id = tid + i * 256;
            u32 row = (u32)(id >> 3), gg = (u32)(id & 7);
            CP16(sb + 8192 + swz128(row, gg), bh + row * 128 + gg * 16);
        }
        CPC(); CPW0();
        __syncthreads();
    }

    float c[8][4];
#pragma unroll
    for (int nt = 0; nt < 8; nt++)
#pragma unroll
        for (int e = 0; e < 4; e++) c[nt][e] = 0.0f;

    const u32 a_row = wm * 16 + (lane & 15);
    const u32 a_g = (u32)(lane >> 4);
    const u32 b_row = wn * 64 + (lane & 7);
    const u32 b_g = (u32)((lane >> 3) & 1);

#pragma unroll
    for (int kt = 0; kt < 4; kt++) {
        u32 ah2[4];
        ldsm4(ah2, sb + swz128(a_row, a_g + kt * 2));
#pragma unroll
        for (int nt = 0; nt < 8; nt++) {
            u32 bh2[2];
            ldsm2(bh2, sb + 8192 + swz128(b_row + nt * 8, b_g + kt * 2));
            mma16816h(c[nt], ah2, bh2);
        }
    }

#pragma unroll
    for (int nt = 0; nt < 8; nt++) {
        float2 o0, o1;
        o0.x = gm * (c[nt][0] + b0) + xva[nt].x;
        o0.y = gm * (c[nt][1] + b0) + xva[nt].y;
        o1.x = gm * (c[nt][2] + b1) + xvb[nt].x;
        o1.y = gm * (c[nt][3] + b1) + xvb[nt].y;
        *(float2*)&out[offs[nt]] = o0;
        *(float2*)&out[offs[nt] + (size_t)8 * HW] = o1;
    }
}

// ---------------------------------------------------------------------------
extern "C" void kernel_launch(void* const* d_in, const int* in_sizes, int n_in,
                              void* d_out, int out_size)
{
    const float* x     = (const float*)d_in[0];
    const float* wq    = (const float*)d_in[1];
    const float* bq    = (const float*)d_in[2];
    const float* wk    = (const float*)d_in[3];
    const float* bk    = (const float*)d_in[4];
    const float* wv    = (const float*)d_in[5];
    const float* bv    = (const float*)d_in[6];
    const float* wsa   = (const float*)d_in[7];
    const float* bsa   = (const float*)d_in[8];
    const float* gamma = (const float*)d_in[9];
    float* out = (float*)d_out;

    cudaFuncSetAttribute(attn_kernel, cudaFuncAttributeMaxDynamicSharedMemorySize, SM_TOTAL);
    cudaFuncSetAttribute(qkv_fused_kernel, cudaFuncAttributeMaxDynamicSharedMemorySize, QF_SMEM);
    cudaFuncSetAttribute(proj_mma_kernel, cudaFuncAttributeMaxDynamicSharedMemorySize, PROJ_SMEM);

    convert_w_kernel<<<32, 256>>>(wq, wk, wv, wsa);
    qkv_fused_kernel<<<dim3(HW / 128, BATCH), 256, QF_SMEM>>>(x, bq, bk, bv);
    attn_kernel<<<dim3(HW / 128, BATCH), 512, SM_TOTAL>>>();
    proj_mma_kernel<<<dim3(HW / 128, CIN / 64, BATCH), 256, PROJ_SMEM>>>(x, bsa, gamma, out);
}